// round 1
// baseline (speedup 1.0000x reference)
#include <cuda_runtime.h>
#include <cuda_bf16.h>
#include <cstdint>

// Problem constants (fixed by the dataset)
#define NN 50000
#define EE 800000
#define C  256          // IN == HID == PROJ == 256

// ---------------------------------------------------------------------------
// Scratch (allocation-free rule: __device__ globals)
// ---------------------------------------------------------------------------
__device__ __align__(16) float g_h[(size_t)NN * C];     // GEMM output (gather source)
__device__ __align__(16) float g_t[(size_t)NN * C];     // aggregation target / layer temp
__device__ __align__(16) float g_dinv[NN];              // deg -> rsqrt(deg)

// ---------------------------------------------------------------------------
// Degree / norm kernels
// ---------------------------------------------------------------------------
__global__ void deg_init(float* dinv, int n) {
    int i = blockIdx.x * blockDim.x + threadIdx.x;
    if (i < n) dinv[i] = 1.0f;   // self-loop contributes 1 to deg
}

__global__ void deg_accum(const int* __restrict__ dst, float* dinv, int e) {
    int i = blockIdx.x * blockDim.x + threadIdx.x;
    if (i < e) atomicAdd(&dinv[dst[i]], 1.0f);
}

__global__ void deg_finish(float* dinv, int n) {
    int i = blockIdx.x * blockDim.x + threadIdx.x;
    if (i < n) dinv[i] = rsqrtf(dinv[i]);   // deg >= 1 always (self-loops)
}

// ---------------------------------------------------------------------------
// SGEMM  H = A @ B  (M x 256 @ 256 x 256), epilogue also writes T = H * dinv^2
// Classic 128x128 tile, BK=8, 256 threads, 8x8 micro-tile per thread.
// ---------------------------------------------------------------------------
#define BM 128
#define BN 128
#define BK 8
#define TM 8
#define TN 8

__global__ __launch_bounds__(256, 2)
void sgemm_epi(const float* __restrict__ A, const float* __restrict__ B,
               float* __restrict__ H, float* __restrict__ T,
               const float* __restrict__ dinv, int M) {
    const int K = C, Nn = C;
    __shared__ float As[BK][BM];
    __shared__ float Bs[BK][BN];

    int tid  = threadIdx.x;
    int tx   = tid & 15;        // 0..15 -> 8 cols each
    int ty   = tid >> 4;        // 0..15 -> 8 rows each
    int row0 = blockIdx.x * BM;
    int col0 = blockIdx.y * BN;

    // A-tile load map: 128 rows x 8 cols = 1024 floats = 256 x float4
    int a_r = tid >> 1;          // 0..127
    int a_c = (tid & 1) * 4;     // 0 or 4
    // B-tile load map: 8 rows x 128 cols
    int b_r = tid >> 5;          // 0..7
    int b_c = (tid & 31) * 4;    // 0..124

    float acc[TM][TN] = {};
    float areg[TM], breg[TN];

    for (int k0 = 0; k0 < K; k0 += BK) {
        int gr = row0 + a_r;
        float4 av = (gr < M)
            ? *(const float4*)(A + (size_t)gr * K + k0 + a_c)
            : make_float4(0.f, 0.f, 0.f, 0.f);
        As[a_c + 0][a_r] = av.x;
        As[a_c + 1][a_r] = av.y;
        As[a_c + 2][a_r] = av.z;
        As[a_c + 3][a_r] = av.w;

        float4 bv = *(const float4*)(B + (size_t)(k0 + b_r) * Nn + col0 + b_c);
        *(float4*)&Bs[b_r][b_c] = bv;
        __syncthreads();

        #pragma unroll
        for (int k = 0; k < BK; k++) {
            #pragma unroll
            for (int i = 0; i < TM; i++) areg[i] = As[k][ty * TM + i];
            #pragma unroll
            for (int j = 0; j < TN; j++) breg[j] = Bs[k][tx * TN + j];
            #pragma unroll
            for (int i = 0; i < TM; i++)
                #pragma unroll
                for (int j = 0; j < TN; j++)
                    acc[i][j] += areg[i] * breg[j];
        }
        __syncthreads();
    }

    // Epilogue: H = acc ; T = acc * dinv^2 (self-loop message, also inits accumulator)
    #pragma unroll
    for (int i = 0; i < TM; i++) {
        int r = row0 + ty * TM + i;
        if (r < M) {
            float dv = dinv[r];
            float d2 = dv * dv;
            #pragma unroll
            for (int j = 0; j < TN; j += 4) {
                int c = col0 + tx * TN + j;
                float4 v = make_float4(acc[i][j], acc[i][j+1], acc[i][j+2], acc[i][j+3]);
                *(float4*)(H + (size_t)r * Nn + c) = v;
                float4 t = make_float4(v.x * d2, v.y * d2, v.z * d2, v.w * d2);
                *(float4*)(T + (size_t)r * Nn + c) = t;
            }
        }
    }
}

// ---------------------------------------------------------------------------
// Edge scatter: out[dst] += h[src] * (dinv[src]*dinv[dst]).
// One warp per edge. Row = 256 floats = 64 float4; each lane handles 2 float4.
// red.global.add.v4.f32 (sm_90+) for vectorized L2 atomics.
// ---------------------------------------------------------------------------
__global__ __launch_bounds__(256)
void scatter_edges(const float* __restrict__ h, float* __restrict__ out,
                   const int* __restrict__ src, const int* __restrict__ dst,
                   const float* __restrict__ dinv, int e_total) {
    int e = blockIdx.x * (blockDim.x >> 5) + (threadIdx.x >> 5);
    if (e >= e_total) return;
    int lane = threadIdx.x & 31;

    int s = __ldg(&src[e]);
    int d = __ldg(&dst[e]);
    float nrm = __ldg(&dinv[s]) * __ldg(&dinv[d]);

    const float4* hs = (const float4*)(h + (size_t)s * C);
    float*        od = out + (size_t)d * C;

    #pragma unroll
    for (int i = 0; i < 2; i++) {
        int idx = lane + i * 32;          // float4 index 0..63
        float4 v = __ldg(&hs[idx]);
        v.x *= nrm; v.y *= nrm; v.z *= nrm; v.w *= nrm;
        asm volatile("red.global.add.v4.f32 [%0], {%1,%2,%3,%4};"
                     :: "l"(od + (size_t)idx * 4),
                        "f"(v.x), "f"(v.y), "f"(v.z), "f"(v.w)
                     : "memory");
    }
}

// ---------------------------------------------------------------------------
// PReLU + bias: out[i,c] = prelu(in[i,c] + b[c], a). float4-vectorized.
// ---------------------------------------------------------------------------
__global__ __launch_bounds__(256)
void prelu_bias(const float* __restrict__ in, const float* __restrict__ b,
                const float* __restrict__ a_ptr, float* __restrict__ out,
                int total4) {
    int i = blockIdx.x * blockDim.x + threadIdx.x;
    if (i >= total4) return;
    float a = __ldg(a_ptr);
    float4 v = ((const float4*)in)[i];
    int c = (i * 4) & (C - 1);
    v.x += __ldg(&b[c + 0]);
    v.y += __ldg(&b[c + 1]);
    v.z += __ldg(&b[c + 2]);
    v.w += __ldg(&b[c + 3]);
    v.x = v.x >= 0.f ? v.x : a * v.x;
    v.y = v.y >= 0.f ? v.y : a * v.y;
    v.z = v.z >= 0.f ? v.z : a * v.z;
    v.w = v.w >= 0.f ? v.w : a * v.w;
    ((float4*)out)[i] = v;
}

// ---------------------------------------------------------------------------
// Launch
// ---------------------------------------------------------------------------
extern "C" void kernel_launch(void* const* d_in, const int* in_sizes, int n_in,
                              void* d_out, int out_size) {
    const float* x  = (const float*)d_in[0];   // [N, 256]
    const float* W1 = (const float*)d_in[1];   // [256, 256]
    const float* b1 = (const float*)d_in[2];   // [256]
    const float* W2 = (const float*)d_in[3];   // [256, 256]
    const float* b2 = (const float*)d_in[4];   // [256]
    const float* a  = (const float*)d_in[5];   // scalar
    const int* eidx = (const int*)d_in[6];     // [2, E]

    const int M = in_sizes[0] / C;             // 50000
    const int E = in_sizes[6] / 2;             // 800000
    const int* src = eidx;
    const int* dst = eidx + E;

    float *hbuf, *tbuf, *dinv;
    cudaGetSymbolAddress((void**)&hbuf, g_h);
    cudaGetSymbolAddress((void**)&tbuf, g_t);
    cudaGetSymbolAddress((void**)&dinv, g_dinv);
    float* outp = (float*)d_out;

    const int total4 = M * C / 4;

    // --- degree / normalization ---
    deg_init  <<<(M + 255) / 256, 256>>>(dinv, M);
    deg_accum <<<(E + 255) / 256, 256>>>(dst, dinv, E);
    deg_finish<<<(M + 255) / 256, 256>>>(dinv, M);

    dim3 ggrid((M + BM - 1) / BM, C / BN);

    // --- layer 1 ---
    // h = x @ W1 ; t = h * dinv^2  (self-loop + accumulator init)
    sgemm_epi<<<ggrid, 256>>>(x, W1, hbuf, tbuf, dinv, M);
    // t[dst] += h[src] * norm
    scatter_edges<<<(E + 7) / 8, 256>>>(hbuf, tbuf, src, dst, dinv, E);
    // h = prelu(t + b1)   (reuse hbuf as layer-2 input)
    prelu_bias<<<(total4 + 255) / 256, 256>>>(tbuf, b1, a, hbuf, total4);

    // --- layer 2 ---
    // t = h @ W2 ; d_out = t * dinv^2
    sgemm_epi<<<ggrid, 256>>>(hbuf, W2, tbuf, outp, dinv, M);
    // d_out[dst] += t[src] * norm
    scatter_edges<<<(E + 7) / 8, 256>>>(tbuf, outp, src, dst, dinv, E);
    // d_out = prelu(d_out + b2)   (in place)
    prelu_bias<<<(total4 + 255) / 256, 256>>>(outp, b2, a, outp, total4);
}